// round 5
// baseline (speedup 1.0000x reference)
#include <cuda_runtime.h>
#include <cuda_bf16.h>
#include <cstdint>

#define NMAX 100000
#define EMAX 800000
#define HDIM 128

// ---------------- static device scratch ------------------------------------
__device__ float g_bufA[NMAX * HDIM];
__device__ float g_bufB[NMAX * HDIM];
__device__ int   g_count[NMAX];
__device__ int   g_excl[NMAX];
__device__ int   g_rowstart[NMAX + 1];
__device__ int   g_cursor[NMAX];
__device__ int   g_col[EMAX];
__device__ int   g_bsum[128];
__device__ float g_sums[6 * 128];            // [layer][sum(128)|sumsq(128)]
__device__ float g_bnm[3 * 128];             // per-layer mean
__device__ float g_bns[3 * 128];             // per-layer rsqrt(var+eps)
__device__ __nv_bfloat16 g_Whi[3 * 16384];   // row-major [k][n] bf16 hi
__device__ __nv_bfloat16 g_Wlo[3 * 16384];   // row-major [k][n] bf16 lo
__device__ int   g_is64;

// ---------------- helpers ---------------------------------------------------
__device__ __forceinline__ uint32_t smem_u32(const void* p) {
    uint32_t a;
    asm("{ .reg .u64 t; cvta.to.shared.u64 t, %1; cvt.u32.u64 %0, t; }" : "=r"(a) : "l"(p));
    return a;
}
__device__ __forceinline__ void ldsm4(uint32_t* r, uint32_t addr) {
    asm volatile("ldmatrix.sync.aligned.m8n8.x4.shared.b16 {%0,%1,%2,%3}, [%4];"
                 : "=r"(r[0]), "=r"(r[1]), "=r"(r[2]), "=r"(r[3]) : "r"(addr));
}
__device__ __forceinline__ void ldsm2t(uint32_t* r, uint32_t addr) {
    asm volatile("ldmatrix.sync.aligned.m8n8.x2.trans.shared.b16 {%0,%1}, [%2];"
                 : "=r"(r[0]), "=r"(r[1]) : "r"(addr));
}
__device__ __forceinline__ void mma16816(float* d, const uint32_t* a, const uint32_t* b) {
    asm volatile("mma.sync.aligned.m16n8k16.row.col.f32.bf16.bf16.f32 "
                 "{%0,%1,%2,%3}, {%4,%5,%6,%7}, {%8,%9}, {%0,%1,%2,%3};"
                 : "+f"(d[0]), "+f"(d[1]), "+f"(d[2]), "+f"(d[3])
                 : "r"(a[0]), "r"(a[1]), "r"(a[2]), "r"(a[3]), "r"(b[0]), "r"(b[1]));
}

// ---------------- init + dtype detection -----------------------------------
__global__ void k_init(int n) {
    int i  = blockIdx.x * blockDim.x + threadIdx.x;
    int st = gridDim.x * blockDim.x;
    for (int k = i; k < n; k += st) g_count[k] = 0;
    for (int k = i; k < 6 * 128; k += st) g_sums[k] = 0.f;
    if (i == 0) g_is64 = 1;
}
__global__ void k_detect(const unsigned* __restrict__ w, int nwords) {
    int i = blockIdx.x * blockDim.x + threadIdx.x;
    int idx = 2 * i + 1;
    if (i < 4096 && idx < nwords) {
        if (w[idx] != 0u) atomicExch(&g_is64, 0);
    }
}
__device__ __forceinline__ int load_idx(const void* ei, long long pos, int is64) {
    if (is64) return (int)((const long long*)ei)[pos];
    return ((const int*)ei)[pos];
}

// ---------------- CSR build ------------------------------------------------
__global__ void k_count(const void* __restrict__ ei, int E, int n) {
    int is64 = g_is64;
    int i  = blockIdx.x * blockDim.x + threadIdx.x;
    int st = gridDim.x * blockDim.x;
    for (int e = i; e < E; e += st) {
        int d = load_idx(ei, e, is64);
        if ((unsigned)d < (unsigned)n) atomicAdd(&g_count[d], 1);
    }
}
__global__ void k_scan1(int n) {
    __shared__ int s[256];
    int tid  = threadIdx.x;
    int base = blockIdx.x * 1024 + tid * 4;
    int v[4];
#pragma unroll
    for (int i = 0; i < 4; i++) v[i] = (base + i < n) ? g_count[base + i] : 0;
    int tsum = v[0] + v[1] + v[2] + v[3];
    s[tid] = tsum;
    __syncthreads();
#pragma unroll
    for (int off = 1; off < 256; off <<= 1) {
        int x = (tid >= off) ? s[tid - off] : 0;
        __syncthreads();
        s[tid] += x;
        __syncthreads();
    }
    int run = s[tid] - tsum;
#pragma unroll
    for (int i = 0; i < 4; i++) {
        if (base + i < n) g_excl[base + i] = run;
        run += v[i];
    }
    if (tid == 255) g_bsum[blockIdx.x] = s[255];
}
__global__ void k_scan2(int nb) {
    __shared__ int s[128];
    int tid = threadIdx.x;
    int v   = (tid < nb) ? g_bsum[tid] : 0;
    s[tid] = v;
    __syncthreads();
#pragma unroll
    for (int off = 1; off < 128; off <<= 1) {
        int x = (tid >= off) ? s[tid - off] : 0;
        __syncthreads();
        s[tid] += x;
        __syncthreads();
    }
    if (tid < nb) g_bsum[tid] = s[tid] - v;
}
__global__ void k_scan3(int n) {
    int i  = blockIdx.x * blockDim.x + threadIdx.x;
    int st = gridDim.x * blockDim.x;
    for (int k = i; k < n; k += st) {
        int r = g_excl[k] + g_bsum[k >> 10];
        g_rowstart[k] = r;
        g_cursor[k]   = r;
    }
    if (i == 0)
        g_rowstart[n] = g_excl[n - 1] + g_bsum[(n - 1) >> 10] + g_count[n - 1];
}
__global__ void k_scatter(const void* __restrict__ ei, int E, int n) {
    int is64 = g_is64;
    int i  = blockIdx.x * blockDim.x + threadIdx.x;
    int st = gridDim.x * blockDim.x;
    for (int e = i; e < E; e += st) {
        int d = load_idx(ei, e, is64);
        if ((unsigned)d >= (unsigned)n) continue;
        int s = load_idx(ei, (long long)E + e, is64);
        if ((unsigned)s >= (unsigned)n) s = d;
        int p = atomicAdd(&g_cursor[d], 1);
        if ((unsigned)p < (unsigned)EMAX) g_col[p] = s;
    }
}

// ---------------- weight prep: fp32 [k][n] -> row-major bf16 hi/lo ----------
__global__ void k_wprep(const float* __restrict__ W, int l) {
    int idx = blockIdx.x * blockDim.x + threadIdx.x;
    if (idx >= 16384) return;
    float v = W[idx];
    __nv_bfloat16 hi = __float2bfloat16_rn(v);
    __nv_bfloat16 lo = __float2bfloat16_rn(v - __bfloat162float(hi));
    g_Whi[l * 16384 + idx] = hi;
    g_Wlo[l * 16384 + idx] = lo;
}

// ---------------- fused aggregate + bf16-split mma GEMM + bias + BN stats ---
// Q = ( Σ_{j∈adj(i)∪{i}} relu(bn(P_j)) ) @ W + b, stats(sum, sumsq) per col.
// 256 thr, 8 warps; warp = 16 rows. Gather with MLP=8 batched loads.
#define PA 136
#define TILEB (128 * PA * 2)           // 34816 B per tile
#define OFF_AHI 0
#define OFF_ALO TILEB
#define OFF_WHI (2 * TILEB)
#define OFF_WLO (3 * TILEB)
#define SMEM_MMA (4 * TILEB)           // 139264 B

__global__ __launch_bounds__(256) void k_fused(
    const float* __restrict__ P, float* __restrict__ Q,
    const __nv_bfloat16* __restrict__ Whi, const __nv_bfloat16* __restrict__ Wlo,
    const float* __restrict__ bias, float* __restrict__ gsum,
    float* __restrict__ gsq, int n,
    const float* __restrict__ bnm, const float* __restrict__ bns)
{
    extern __shared__ char sm[];
    int tid  = threadIdx.x;
    int lane = tid & 31;
    int warp = tid >> 5;
    int r0g  = blockIdx.x * 128;

    // ---- W tiles first (independent loads, overlap with gather) ------------
    for (int i = tid; i < 4096; i += 256) {     // k = i>>5, c4 = (i&31)*4
        int k = i >> 5, c4 = (i & 31) * 4;
        uint2 h = *(const uint2*)((const char*)Whi + k * 256 + c4 * 2);
        uint2 l = *(const uint2*)((const char*)Wlo + k * 256 + c4 * 2);
        *(uint2*)(sm + OFF_WHI + k * (PA * 2) + c4 * 2) = h;
        *(uint2*)(sm + OFF_WLO + k * (PA * 2) + c4 * 2) = l;
    }

    // ---- gather + BN(prev)+ReLU + bf16 split into A tiles ------------------
    bool dobn = (bnm != nullptr);
    float4 m4 = make_float4(0.f, 0.f, 0.f, 0.f);
    float4 s4 = make_float4(1.f, 1.f, 1.f, 1.f);
    if (dobn) {
        m4 = ((const float4*)bnm)[lane];
        s4 = ((const float4*)bns)[lane];
    }
    const float4* P4 = (const float4*)P;

    for (int rr = 0; rr < 16; rr++) {
        int rloc = warp * 16 + rr;
        int row  = r0g + rloc;
        float4 acc = make_float4(0.f, 0.f, 0.f, 0.f);
        if (row < n) {
            acc = P4[(size_t)row * 32 + lane];     // self loop
            if (dobn) {
                acc.x = fmaxf((acc.x - m4.x) * s4.x, 0.f);
                acc.y = fmaxf((acc.y - m4.y) * s4.y, 0.f);
                acc.z = fmaxf((acc.z - m4.z) * s4.z, 0.f);
                acc.w = fmaxf((acc.w - m4.w) * s4.w, 0.f);
            }
            int s = g_rowstart[row];
            int t = g_rowstart[row + 1];
            for (int p = s; p < t; p += 8) {
                int cnt = min(8, t - p);
                float4 r[8];
#pragma unroll
                for (int u = 0; u < 8; u++) {      // MLP=8 independent loads
                    if (u < cnt) {
                        int j = g_col[p + u];
                        r[u] = P4[(size_t)j * 32 + lane];
                    }
                }
#pragma unroll
                for (int u = 0; u < 8; u++) {
                    if (u < cnt) {
                        float4 v = r[u];
                        if (dobn) {
                            v.x = fmaxf((v.x - m4.x) * s4.x, 0.f);
                            v.y = fmaxf((v.y - m4.y) * s4.y, 0.f);
                            v.z = fmaxf((v.z - m4.z) * s4.z, 0.f);
                            v.w = fmaxf((v.w - m4.w) * s4.w, 0.f);
                        }
                        acc.x += v.x; acc.y += v.y; acc.z += v.z; acc.w += v.w;
                    }
                }
            }
        }
        // bf16 hi/lo split -> smem tiles (cols lane*4 .. lane*4+3)
        __nv_bfloat16 h0 = __float2bfloat16_rn(acc.x), h1 = __float2bfloat16_rn(acc.y);
        __nv_bfloat16 h2 = __float2bfloat16_rn(acc.z), h3 = __float2bfloat16_rn(acc.w);
        __nv_bfloat16 l0 = __float2bfloat16_rn(acc.x - __bfloat162float(h0));
        __nv_bfloat16 l1 = __float2bfloat16_rn(acc.y - __bfloat162float(h1));
        __nv_bfloat16 l2 = __float2bfloat16_rn(acc.z - __bfloat162float(h2));
        __nv_bfloat16 l3 = __float2bfloat16_rn(acc.w - __bfloat162float(h3));
        uint2 ph = make_uint2(
            (uint32_t)__bfloat16_as_ushort(h0) | ((uint32_t)__bfloat16_as_ushort(h1) << 16),
            (uint32_t)__bfloat16_as_ushort(h2) | ((uint32_t)__bfloat16_as_ushort(h3) << 16));
        uint2 pl = make_uint2(
            (uint32_t)__bfloat16_as_ushort(l0) | ((uint32_t)__bfloat16_as_ushort(l1) << 16),
            (uint32_t)__bfloat16_as_ushort(l2) | ((uint32_t)__bfloat16_as_ushort(l3) << 16));
        *(uint2*)(sm + OFF_AHI + rloc * (PA * 2) + lane * 8) = ph;
        *(uint2*)(sm + OFF_ALO + rloc * (PA * 2) + lane * 8) = pl;
    }
    __syncthreads();

    // ---- mma mainloop: D = Ahi*Whi + Alo*Whi + Ahi*Wlo ---------------------
    int m  = lane >> 3, ri = lane & 7;
    int rowA = warp * 16 + (m & 1) * 8 + ri;
    uint32_t aHi = smem_u32(sm + OFF_AHI) + rowA * (PA * 2) + (m >> 1) * 16;
    uint32_t aLo = smem_u32(sm + OFF_ALO) + rowA * (PA * 2) + (m >> 1) * 16;
    int l16 = lane & 15;
    int rowB = (l16 >> 3) * 8 + (l16 & 7);
    uint32_t bHi = smem_u32(sm + OFF_WHI) + rowB * (PA * 2);
    uint32_t bLo = smem_u32(sm + OFF_WLO) + rowB * (PA * 2);

    float acc[16][4];
#pragma unroll
    for (int t = 0; t < 16; t++)
#pragma unroll
        for (int j = 0; j < 4; j++) acc[t][j] = 0.f;

#pragma unroll
    for (int kc = 0; kc < 8; kc++) {
        uint32_t ah[4], al[4];
        ldsm4(ah, aHi + kc * 32);
        ldsm4(al, aLo + kc * 32);
        uint32_t kb = kc * 16 * (PA * 2);
#pragma unroll
        for (int nt = 0; nt < 16; nt++) {
            uint32_t bh[2], bl[2];
            ldsm2t(bh, bHi + kb + nt * 16);
            ldsm2t(bl, bLo + kb + nt * 16);
            mma16816(acc[nt], ah, bh);
            mma16816(acc[nt], al, bh);
            mma16816(acc[nt], ah, bl);
        }
    }
    __syncthreads();   // smem tiles dead; reuse for stats

    // ---- epilogue: bias, store to Q, BN partial stats ----------------------
    float* sred  = (float*)sm;            // [8][128]
    float* sredq = (float*)sm + 1024;     // [8][128]
    int lr = lane >> 2;
    int lc = lane & 3;
    int row0 = r0g + warp * 16 + lr;
    int row1 = row0 + 8;
    bool v0 = row0 < n, v1 = row1 < n;
#pragma unroll
    for (int nt = 0; nt < 16; nt++) {
        int c0 = nt * 8 + lc * 2;
        float b0v = __ldg(bias + c0), b1v = __ldg(bias + c0 + 1);
        float y00 = acc[nt][0] + b0v, y01 = acc[nt][1] + b1v;
        float y10 = acc[nt][2] + b0v, y11 = acc[nt][3] + b1v;
        if (v0) *(float2*)&Q[(size_t)row0 * 128 + c0] = make_float2(y00, y01);
        if (v1) *(float2*)&Q[(size_t)row1 * 128 + c0] = make_float2(y10, y11);
        float s0 = (v0 ? y00 : 0.f) + (v1 ? y10 : 0.f);
        float s1 = (v0 ? y01 : 0.f) + (v1 ? y11 : 0.f);
        float q0 = (v0 ? y00 * y00 : 0.f) + (v1 ? y10 * y10 : 0.f);
        float q1 = (v0 ? y01 * y01 : 0.f) + (v1 ? y11 * y11 : 0.f);
#pragma unroll
        for (int o = 4; o < 32; o <<= 1) {
            s0 += __shfl_xor_sync(0xffffffffu, s0, o);
            s1 += __shfl_xor_sync(0xffffffffu, s1, o);
            q0 += __shfl_xor_sync(0xffffffffu, q0, o);
            q1 += __shfl_xor_sync(0xffffffffu, q1, o);
        }
        if (lr == 0) {
            sred [warp * 128 + c0]     = s0;
            sred [warp * 128 + c0 + 1] = s1;
            sredq[warp * 128 + c0]     = q0;
            sredq[warp * 128 + c0 + 1] = q1;
        }
    }
    __syncthreads();
    if (tid < 128) {
        float s = 0.f, q = 0.f;
#pragma unroll
        for (int w = 0; w < 8; w++) {
            s += sred [w * 128 + tid];
            q += sredq[w * 128 + tid];
        }
        atomicAdd(&gsum[tid], s);
        atomicAdd(&gsq[tid], q);
    }
}

// ---------------- BN finalize (per layer, tiny) -----------------------------
__global__ void k_bnfin(int l, int n) {
    int c = threadIdx.x;
    float inv_n = 1.0f / (float)n;
    float m = g_sums[l * 256 + c] * inv_n;
    float v = g_sums[l * 256 + 128 + c] * inv_n - m * m;
    g_bnm[l * 128 + c] = m;
    g_bns[l * 128 + c] = rsqrtf(v + 1e-5f);
}

// ---------------- final GEMM 128 -> 40 + bias (BN+ReLU fused on load) ------
// 128 threads, 128 rows/block, thread tile 8x5 (FMA:LDS ratio ~3).
#define SMEM40 ((128 * 132 + 128 * 40) * 4)
__global__ __launch_bounds__(128) void k_gemm40(
    const float* __restrict__ A, const float* __restrict__ W,
    const float* __restrict__ bias, float* __restrict__ out, int n,
    const float* __restrict__ bnm, const float* __restrict__ bns)
{
    extern __shared__ float smf[];
    float* As = smf;              // [128][132]
    float* Ws = smf + 128 * 132;  // [128][40]
    int tid = threadIdx.x;
    int r0  = blockIdx.x * 128;

    for (int i = tid; i < 4096; i += 128) {
        int row = i >> 5, k4 = i & 31;
        float4 v = make_float4(0.f, 0.f, 0.f, 0.f);
        if (r0 + row < n) {
            v = ((const float4*)A)[(size_t)(r0 + row) * 32 + k4];
            float4 m4 = ((const float4*)bnm)[k4];
            float4 s4 = ((const float4*)bns)[k4];
            v.x = fmaxf((v.x - m4.x) * s4.x, 0.f);
            v.y = fmaxf((v.y - m4.y) * s4.y, 0.f);
            v.z = fmaxf((v.z - m4.z) * s4.z, 0.f);
            v.w = fmaxf((v.w - m4.w) * s4.w, 0.f);
        }
        float* d = &As[row * 132 + k4 * 4];
        d[0] = v.x; d[1] = v.y; d[2] = v.z; d[3] = v.w;
    }
    for (int i = tid; i < 1280; i += 128)
        ((float4*)Ws)[i] = ((const float4*)W)[i];
    __syncthreads();

    int tr = tid >> 3;   // 0..15 -> rows tr*8 .. +7
    int tc = tid & 7;    // 0..7  -> cols tc*5 .. +4
    float acc[8][5];
#pragma unroll
    for (int i = 0; i < 8; i++)
#pragma unroll
        for (int j = 0; j < 5; j++) acc[i][j] = 0.f;

    for (int k = 0; k < 128; k += 4) {
        float4 a[8];
#pragma unroll
        for (int i = 0; i < 8; i++) a[i] = *(const float4*)&As[(tr * 8 + i) * 132 + k];
#pragma unroll
        for (int kk = 0; kk < 4; kk++) {
            float b[5];
#pragma unroll
            for (int j = 0; j < 5; j++) b[j] = Ws[(k + kk) * 40 + tc * 5 + j];
#pragma unroll
            for (int i = 0; i < 8; i++) {
                float av = ((const float*)&a[i])[kk];
#pragma unroll
                for (int j = 0; j < 5; j++) acc[i][j] += av * b[j];
            }
        }
    }
    float br[5];
#pragma unroll
    for (int j = 0; j < 5; j++) br[j] = bias[tc * 5 + j];
#pragma unroll
    for (int i = 0; i < 8; i++) {
        int row = r0 + tr * 8 + i;
        if (row < n) {
#pragma unroll
            for (int j = 0; j < 5; j++)
                out[(size_t)row * 40 + tc * 5 + j] = acc[i][j] + br[j];
        }
    }
}

// ---------------- launcher -------------------------------------------------
extern "C" void kernel_launch(void* const* d_in, const int* in_sizes, int n_in,
                              void* d_out, int out_size)
{
    const float* x  = (const float*)d_in[0];
    const void*  ei = d_in[1];
    const float* W0 = (const float*)d_in[2];
    const float* b0 = (const float*)d_in[3];
    const float* W1 = (const float*)d_in[4];
    const float* b1 = (const float*)d_in[5];
    const float* W2 = (const float*)d_in[6];
    const float* b2 = (const float*)d_in[7];
    const float* Wl = (const float*)d_in[8];
    const float* bl = (const float*)d_in[9];
    float* out = (float*)d_out;

    int n = in_sizes[0] / HDIM;
    int E = in_sizes[1] / 2;

    float *bufA, *bufB, *sums, *bnm, *bns;
    __nv_bfloat16 *whi, *wlo;
    cudaGetSymbolAddress((void**)&bufA, g_bufA);
    cudaGetSymbolAddress((void**)&bufB, g_bufB);
    cudaGetSymbolAddress((void**)&sums, g_sums);
    cudaGetSymbolAddress((void**)&bnm,  g_bnm);
    cudaGetSymbolAddress((void**)&bns,  g_bns);
    cudaGetSymbolAddress((void**)&whi,  g_Whi);
    cudaGetSymbolAddress((void**)&wlo,  g_Wlo);

    cudaFuncSetAttribute(k_fused,  cudaFuncAttributeMaxDynamicSharedMemorySize, SMEM_MMA);
    cudaFuncSetAttribute(k_gemm40, cudaFuncAttributeMaxDynamicSharedMemorySize, SMEM40);

    int nb = (n + 1023) >> 10;

    // CSR build (once; reused by all 3 layers)
    k_init<<<256, 256>>>(n);
    k_detect<<<16, 256>>>((const unsigned*)ei, in_sizes[1]);
    k_count<<<(E + 255) / 256, 256>>>(ei, E, n);
    k_scan1<<<nb, 256>>>(n);
    k_scan2<<<1, 128>>>(nb);
    k_scan3<<<(n + 255) / 256, 256>>>(n);
    k_scatter<<<(E + 255) / 256, 256>>>(ei, E, n);

    // weight prep (independent of CSR)
    k_wprep<<<64, 256>>>(W0, 0);
    k_wprep<<<64, 256>>>(W1, 1);
    k_wprep<<<64, 256>>>(W2, 2);

    const float* bs_[3] = { b0, b1, b2 };
    int ngrid = (n + 127) / 128;
    const float* P = x;
    float* bufs[2] = { bufA, bufB };
    for (int l = 0; l < 3; l++) {
        float* Q = bufs[l & 1];
        const float* pm  = (l == 0) ? nullptr : bnm + (l - 1) * 128;
        const float* psd = (l == 0) ? nullptr : bns + (l - 1) * 128;
        k_fused<<<ngrid, 256, SMEM_MMA>>>(P, Q, whi + l * 16384, wlo + l * 16384,
                                          bs_[l], sums + l * 256,
                                          sums + l * 256 + 128, n, pm, psd);
        k_bnfin<<<1, 128>>>(l, n);
        P = Q;
    }
    k_gemm40<<<(n + 127) / 128, 128, SMEM40>>>(P, Wl, bl, out, n,
                                               bnm + 2 * 128, bns + 2 * 128);
}

// round 6
// speedup vs baseline: 1.4310x; 1.4310x over previous
#include <cuda_runtime.h>
#include <cuda_bf16.h>
#include <cstdint>

#define NMAX 100000
#define EMAX 800000
#define HDIM 128

// ---------------- static device scratch ------------------------------------
__device__ float g_bufA[NMAX * HDIM];
__device__ float g_bufB[NMAX * HDIM];
__device__ int   g_count[NMAX];
__device__ int   g_excl[NMAX];
__device__ int   g_rowstart[NMAX + 1];
__device__ int   g_cursor[NMAX];
__device__ int   g_col[EMAX];
__device__ int   g_bsum[128];
__device__ float g_sums[6 * 128];            // [layer][sum(128)|sumsq(128)]
__device__ float g_bnm[3 * 128];             // per-layer mean
__device__ float g_bns[3 * 128];             // per-layer rsqrt(var+eps)
__device__ __nv_bfloat16 g_Whi[3 * 16384];   // row-major [k][n] bf16 hi
__device__ __nv_bfloat16 g_Wlo[3 * 16384];   // row-major [k][n] bf16 lo
__device__ int   g_is64;

// ---------------- helpers ---------------------------------------------------
__device__ __forceinline__ uint32_t smem_u32(const void* p) {
    uint32_t a;
    asm("{ .reg .u64 t; cvta.to.shared.u64 t, %1; cvt.u32.u64 %0, t; }" : "=r"(a) : "l"(p));
    return a;
}
__device__ __forceinline__ void ldsm4(uint32_t* r, uint32_t addr) {
    asm volatile("ldmatrix.sync.aligned.m8n8.x4.shared.b16 {%0,%1,%2,%3}, [%4];"
                 : "=r"(r[0]), "=r"(r[1]), "=r"(r[2]), "=r"(r[3]) : "r"(addr));
}
__device__ __forceinline__ void ldsm2t(uint32_t* r, uint32_t addr) {
    asm volatile("ldmatrix.sync.aligned.m8n8.x2.trans.shared.b16 {%0,%1}, [%2];"
                 : "=r"(r[0]), "=r"(r[1]) : "r"(addr));
}
__device__ __forceinline__ void mma16816(float* d, const uint32_t* a, const uint32_t* b) {
    asm volatile("mma.sync.aligned.m16n8k16.row.col.f32.bf16.bf16.f32 "
                 "{%0,%1,%2,%3}, {%4,%5,%6,%7}, {%8,%9}, {%0,%1,%2,%3};"
                 : "+f"(d[0]), "+f"(d[1]), "+f"(d[2]), "+f"(d[3])
                 : "r"(a[0]), "r"(a[1]), "r"(a[2]), "r"(a[3]), "r"(b[0]), "r"(b[1]));
}
__device__ __forceinline__ float4 bn_relu4(float4 v, float4 m4, float4 s4) {
    v.x = fmaxf((v.x - m4.x) * s4.x, 0.f);
    v.y = fmaxf((v.y - m4.y) * s4.y, 0.f);
    v.z = fmaxf((v.z - m4.z) * s4.z, 0.f);
    v.w = fmaxf((v.w - m4.w) * s4.w, 0.f);
    return v;
}

// ---------------- init + dtype detection -----------------------------------
__global__ void k_init(int n) {
    int i  = blockIdx.x * blockDim.x + threadIdx.x;
    int st = gridDim.x * blockDim.x;
    for (int k = i; k < n; k += st) g_count[k] = 0;
    for (int k = i; k < 6 * 128; k += st) g_sums[k] = 0.f;
    if (i == 0) g_is64 = 1;
}
__global__ void k_detect(const unsigned* __restrict__ w, int nwords) {
    int i = blockIdx.x * blockDim.x + threadIdx.x;
    int idx = 2 * i + 1;
    if (i < 4096 && idx < nwords) {
        if (w[idx] != 0u) atomicExch(&g_is64, 0);
    }
}
__device__ __forceinline__ int load_idx(const void* ei, long long pos, int is64) {
    if (is64) return (int)((const long long*)ei)[pos];
    return ((const int*)ei)[pos];
}

// ---------------- CSR build ------------------------------------------------
__global__ void k_count(const void* __restrict__ ei, int E, int n) {
    int is64 = g_is64;
    int i  = blockIdx.x * blockDim.x + threadIdx.x;
    int st = gridDim.x * blockDim.x;
    for (int e = i; e < E; e += st) {
        int d = load_idx(ei, e, is64);
        if ((unsigned)d < (unsigned)n) atomicAdd(&g_count[d], 1);
    }
}
__global__ void k_scan1(int n) {
    __shared__ int s[256];
    int tid  = threadIdx.x;
    int base = blockIdx.x * 1024 + tid * 4;
    int v[4];
#pragma unroll
    for (int i = 0; i < 4; i++) v[i] = (base + i < n) ? g_count[base + i] : 0;
    int tsum = v[0] + v[1] + v[2] + v[3];
    s[tid] = tsum;
    __syncthreads();
#pragma unroll
    for (int off = 1; off < 256; off <<= 1) {
        int x = (tid >= off) ? s[tid - off] : 0;
        __syncthreads();
        s[tid] += x;
        __syncthreads();
    }
    int run = s[tid] - tsum;
#pragma unroll
    for (int i = 0; i < 4; i++) {
        if (base + i < n) g_excl[base + i] = run;
        run += v[i];
    }
    if (tid == 255) g_bsum[blockIdx.x] = s[255];
}
__global__ void k_scan2(int nb) {
    __shared__ int s[128];
    int tid = threadIdx.x;
    int v   = (tid < nb) ? g_bsum[tid] : 0;
    s[tid] = v;
    __syncthreads();
#pragma unroll
    for (int off = 1; off < 128; off <<= 1) {
        int x = (tid >= off) ? s[tid - off] : 0;
        __syncthreads();
        s[tid] += x;
        __syncthreads();
    }
    if (tid < nb) g_bsum[tid] = s[tid] - v;
}
__global__ void k_scan3(int n) {
    int i  = blockIdx.x * blockDim.x + threadIdx.x;
    int st = gridDim.x * blockDim.x;
    for (int k = i; k < n; k += st) {
        int r = g_excl[k] + g_bsum[k >> 10];
        g_rowstart[k] = r;
        g_cursor[k]   = r;
    }
    if (i == 0)
        g_rowstart[n] = g_excl[n - 1] + g_bsum[(n - 1) >> 10] + g_count[n - 1];
}
__global__ void k_scatter(const void* __restrict__ ei, int E, int n) {
    int is64 = g_is64;
    int i  = blockIdx.x * blockDim.x + threadIdx.x;
    int st = gridDim.x * blockDim.x;
    for (int e = i; e < E; e += st) {
        int d = load_idx(ei, e, is64);
        if ((unsigned)d >= (unsigned)n) continue;
        int s = load_idx(ei, (long long)E + e, is64);
        if ((unsigned)s >= (unsigned)n) s = d;
        int p = atomicAdd(&g_cursor[d], 1);
        if ((unsigned)p < (unsigned)EMAX) g_col[p] = s;
    }
}

// ---------------- weight prep: fp32 [k][n] -> row-major bf16 hi/lo ----------
__global__ void k_wprep(const float* __restrict__ W, int l) {
    int idx = blockIdx.x * blockDim.x + threadIdx.x;
    if (idx >= 16384) return;
    float v = W[idx];
    __nv_bfloat16 hi = __float2bfloat16_rn(v);
    __nv_bfloat16 lo = __float2bfloat16_rn(v - __bfloat162float(hi));
    g_Whi[l * 16384 + idx] = hi;
    g_Wlo[l * 16384 + idx] = lo;
}

// ---------------- aggregation (+ fused BN+ReLU of prev layer), MLP=4 -------
__global__ void k_aggregate(const float* __restrict__ P, float* __restrict__ Q, int n,
                            const float* __restrict__ bnm, const float* __restrict__ bns) {
    int warp = (blockIdx.x * blockDim.x + threadIdx.x) >> 5;
    int lane = threadIdx.x & 31;
    if (warp >= n) return;
    bool dobn = (bnm != nullptr);
    float4 m4 = make_float4(0.f, 0.f, 0.f, 0.f);
    float4 s4 = make_float4(1.f, 1.f, 1.f, 1.f);
    if (dobn) {
        m4 = ((const float4*)bnm)[lane];
        s4 = ((const float4*)bns)[lane];
    }
    const float4* P4 = (const float4*)P;
    float4 acc = P4[(size_t)warp * 32 + lane];
    if (dobn) acc = bn_relu4(acc, m4, s4);
    int s = g_rowstart[warp];
    int t = g_rowstart[warp + 1];
    for (int p = s; p < t; p += 32) {
        int cnt = min(32, t - p);
        int j = (lane < cnt) ? g_col[p + lane] : 0;
        int q = 0;
        for (; q + 4 <= cnt; q += 4) {          // 4 independent loads in flight
            int j0 = __shfl_sync(0xffffffffu, j, q);
            int j1 = __shfl_sync(0xffffffffu, j, q + 1);
            int j2 = __shfl_sync(0xffffffffu, j, q + 2);
            int j3 = __shfl_sync(0xffffffffu, j, q + 3);
            float4 r0 = P4[(size_t)j0 * 32 + lane];
            float4 r1 = P4[(size_t)j1 * 32 + lane];
            float4 r2 = P4[(size_t)j2 * 32 + lane];
            float4 r3 = P4[(size_t)j3 * 32 + lane];
            if (dobn) {
                r0 = bn_relu4(r0, m4, s4); r1 = bn_relu4(r1, m4, s4);
                r2 = bn_relu4(r2, m4, s4); r3 = bn_relu4(r3, m4, s4);
            }
            acc.x += r0.x + r1.x + r2.x + r3.x;
            acc.y += r0.y + r1.y + r2.y + r3.y;
            acc.z += r0.z + r1.z + r2.z + r3.z;
            acc.w += r0.w + r1.w + r2.w + r3.w;
        }
        for (; q < cnt; q++) {
            int jj = __shfl_sync(0xffffffffu, j, q);
            float4 r = P4[(size_t)jj * 32 + lane];
            if (dobn) r = bn_relu4(r, m4, s4);
            acc.x += r.x; acc.y += r.y; acc.z += r.z; acc.w += r.w;
        }
    }
    ((float4*)Q)[(size_t)warp * 32 + lane] = acc;
}

// ---------------- mma.sync bf16 GEMM 64x128 (in place) + bias + BN stats ----
// 3-term bf16 split: D = Ahi*Whi + Alo*Whi + Ahi*Wlo.  128 thr, 4 warps,
// warp = 16 rows x 128 cols. 64 rows/CTA -> smem 104448 B -> 2 CTAs/SM.
#define PA 136
#define ATILEB (64 * PA * 2)            // 17408 B
#define WTILEB (128 * PA * 2)           // 34816 B
#define OFF_AHI 0
#define OFF_ALO ATILEB
#define OFF_WHI (2 * ATILEB)
#define OFF_WLO (2 * ATILEB + WTILEB)
#define SMEM_MMA (2 * ATILEB + 2 * WTILEB)   // 104448 B

__global__ __launch_bounds__(128) void k_gemm_mma(
    float* __restrict__ A, const __nv_bfloat16* __restrict__ Whi,
    const __nv_bfloat16* __restrict__ Wlo, const float* __restrict__ bias,
    float* __restrict__ gsum, float* __restrict__ gsq, int n)
{
    extern __shared__ char sm[];
    int tid  = threadIdx.x;
    int lane = tid & 31;
    int warp = tid >> 5;
    int r0g  = blockIdx.x * 64;

    // ---- fill A hi/lo tiles (64 rows, bf16, pitch 136) ---------------------
    const float4* A4 = (const float4*)A;
    for (int i = tid; i < 2048; i += 128) {     // row = i>>5, c4 = (i&31)*4
        int row = i >> 5, c4 = (i & 31) * 4;
        float4 v = make_float4(0.f, 0.f, 0.f, 0.f);
        if (r0g + row < n) v = A4[(size_t)(r0g + row) * 32 + (i & 31)];
        __nv_bfloat16 h0 = __float2bfloat16_rn(v.x), h1 = __float2bfloat16_rn(v.y);
        __nv_bfloat16 h2 = __float2bfloat16_rn(v.z), h3 = __float2bfloat16_rn(v.w);
        __nv_bfloat16 l0 = __float2bfloat16_rn(v.x - __bfloat162float(h0));
        __nv_bfloat16 l1 = __float2bfloat16_rn(v.y - __bfloat162float(h1));
        __nv_bfloat16 l2 = __float2bfloat16_rn(v.z - __bfloat162float(h2));
        __nv_bfloat16 l3 = __float2bfloat16_rn(v.w - __bfloat162float(h3));
        uint2 ph = make_uint2(
            (uint32_t)__bfloat16_as_ushort(h0) | ((uint32_t)__bfloat16_as_ushort(h1) << 16),
            (uint32_t)__bfloat16_as_ushort(h2) | ((uint32_t)__bfloat16_as_ushort(h3) << 16));
        uint2 pl = make_uint2(
            (uint32_t)__bfloat16_as_ushort(l0) | ((uint32_t)__bfloat16_as_ushort(l1) << 16),
            (uint32_t)__bfloat16_as_ushort(l2) | ((uint32_t)__bfloat16_as_ushort(l3) << 16));
        *(uint2*)(sm + OFF_AHI + row * (PA * 2) + c4 * 2) = ph;
        *(uint2*)(sm + OFF_ALO + row * (PA * 2) + c4 * 2) = pl;
    }
    // ---- fill W hi/lo tiles ------------------------------------------------
    for (int i = tid; i < 4096; i += 128) {     // k = i>>5, c4 = (i&31)*4
        int k = i >> 5, c4 = (i & 31) * 4;
        uint2 h = *(const uint2*)((const char*)Whi + k * 256 + c4 * 2);
        uint2 l = *(const uint2*)((const char*)Wlo + k * 256 + c4 * 2);
        *(uint2*)(sm + OFF_WHI + k * (PA * 2) + c4 * 2) = h;
        *(uint2*)(sm + OFF_WLO + k * (PA * 2) + c4 * 2) = l;
    }
    __syncthreads();

    // ---- mma mainloop ------------------------------------------------------
    int m  = lane >> 3, ri = lane & 7;
    int rowA = warp * 16 + (m & 1) * 8 + ri;
    uint32_t aHi = smem_u32(sm + OFF_AHI) + rowA * (PA * 2) + (m >> 1) * 16;
    uint32_t aLo = smem_u32(sm + OFF_ALO) + rowA * (PA * 2) + (m >> 1) * 16;
    int l16 = lane & 15;
    int rowB = (l16 >> 3) * 8 + (l16 & 7);
    uint32_t bHi = smem_u32(sm + OFF_WHI) + rowB * (PA * 2);
    uint32_t bLo = smem_u32(sm + OFF_WLO) + rowB * (PA * 2);

    float acc[16][4];
#pragma unroll
    for (int t = 0; t < 16; t++)
#pragma unroll
        for (int j = 0; j < 4; j++) acc[t][j] = 0.f;

#pragma unroll
    for (int kc = 0; kc < 8; kc++) {
        uint32_t ah[4], al[4];
        ldsm4(ah, aHi + kc * 32);
        ldsm4(al, aLo + kc * 32);
        uint32_t kb = kc * 16 * (PA * 2);
#pragma unroll
        for (int nt = 0; nt < 16; nt++) {
            uint32_t bh[2], bl[2];
            ldsm2t(bh, bHi + kb + nt * 16);
            ldsm2t(bl, bLo + kb + nt * 16);
            mma16816(acc[nt], ah, bh);
            mma16816(acc[nt], al, bh);
            mma16816(acc[nt], ah, bl);
        }
    }
    __syncthreads();   // smem tiles dead; reuse for stats

    // ---- epilogue: bias, store, BN partial stats ---------------------------
    float* sred  = (float*)sm;            // [4][128]
    float* sredq = (float*)sm + 512;      // [4][128]
    int lr = lane >> 2;
    int lc = lane & 3;
    int row0 = r0g + warp * 16 + lr;
    int row1 = row0 + 8;
    bool v0 = row0 < n, v1 = row1 < n;
#pragma unroll
    for (int nt = 0; nt < 16; nt++) {
        int c0 = nt * 8 + lc * 2;
        float b0v = __ldg(bias + c0), b1v = __ldg(bias + c0 + 1);
        float y00 = acc[nt][0] + b0v, y01 = acc[nt][1] + b1v;
        float y10 = acc[nt][2] + b0v, y11 = acc[nt][3] + b1v;
        if (v0) *(float2*)&A[(size_t)row0 * 128 + c0] = make_float2(y00, y01);
        if (v1) *(float2*)&A[(size_t)row1 * 128 + c0] = make_float2(y10, y11);
        float s0 = (v0 ? y00 : 0.f) + (v1 ? y10 : 0.f);
        float s1 = (v0 ? y01 : 0.f) + (v1 ? y11 : 0.f);
        float q0 = (v0 ? y00 * y00 : 0.f) + (v1 ? y10 * y10 : 0.f);
        float q1 = (v0 ? y01 * y01 : 0.f) + (v1 ? y11 * y11 : 0.f);
#pragma unroll
        for (int o = 4; o < 32; o <<= 1) {
            s0 += __shfl_xor_sync(0xffffffffu, s0, o);
            s1 += __shfl_xor_sync(0xffffffffu, s1, o);
            q0 += __shfl_xor_sync(0xffffffffu, q0, o);
            q1 += __shfl_xor_sync(0xffffffffu, q1, o);
        }
        if (lr == 0) {
            sred [warp * 128 + c0]     = s0;
            sred [warp * 128 + c0 + 1] = s1;
            sredq[warp * 128 + c0]     = q0;
            sredq[warp * 128 + c0 + 1] = q1;
        }
    }
    __syncthreads();
    if (tid < 128) {
        float s = 0.f, q = 0.f;
#pragma unroll
        for (int w = 0; w < 4; w++) {
            s += sred [w * 128 + tid];
            q += sredq[w * 128 + tid];
        }
        atomicAdd(&gsum[tid], s);
        atomicAdd(&gsq[tid], q);
    }
}

// ---------------- BN finalize (per layer, tiny) -----------------------------
__global__ void k_bnfin(int l, int n) {
    int c = threadIdx.x;
    float inv_n = 1.0f / (float)n;
    float m = g_sums[l * 256 + c] * inv_n;
    float v = g_sums[l * 256 + 128 + c] * inv_n - m * m;
    g_bnm[l * 128 + c] = m;
    g_bns[l * 128 + c] = rsqrtf(v + 1e-5f);
}

// ---------------- final GEMM 128 -> 40 + bias (BN+ReLU fused on load) ------
#define SMEM40 ((128 * 132 + 128 * 40) * 4)
__global__ __launch_bounds__(128) void k_gemm40(
    const float* __restrict__ A, const float* __restrict__ W,
    const float* __restrict__ bias, float* __restrict__ out, int n,
    const float* __restrict__ bnm, const float* __restrict__ bns)
{
    extern __shared__ float smf[];
    float* As = smf;              // [128][132]
    float* Ws = smf + 128 * 132;  // [128][40]
    int tid = threadIdx.x;
    int r0  = blockIdx.x * 128;

    for (int i = tid; i < 4096; i += 128) {
        int row = i >> 5, k4 = i & 31;
        float4 v = make_float4(0.f, 0.f, 0.f, 0.f);
        if (r0 + row < n) {
            v = ((const float4*)A)[(size_t)(r0 + row) * 32 + k4];
            float4 m4 = ((const float4*)bnm)[k4];
            float4 s4 = ((const float4*)bns)[k4];
            v = bn_relu4(v, m4, s4);
        }
        float* d = &As[row * 132 + k4 * 4];
        d[0] = v.x; d[1] = v.y; d[2] = v.z; d[3] = v.w;
    }
    for (int i = tid; i < 1280; i += 128)
        ((float4*)Ws)[i] = ((const float4*)W)[i];
    __syncthreads();

    int tr = tid >> 3;   // 0..15 -> rows tr*8 .. +7
    int tc = tid & 7;    // 0..7  -> cols tc*5 .. +4
    float acc[8][5];
#pragma unroll
    for (int i = 0; i < 8; i++)
#pragma unroll
        for (int j = 0; j < 5; j++) acc[i][j] = 0.f;

    for (int k = 0; k < 128; k += 4) {
        float4 a[8];
#pragma unroll
        for (int i = 0; i < 8; i++) a[i] = *(const float4*)&As[(tr * 8 + i) * 132 + k];
#pragma unroll
        for (int kk = 0; kk < 4; kk++) {
            float b[5];
#pragma unroll
            for (int j = 0; j < 5; j++) b[j] = Ws[(k + kk) * 40 + tc * 5 + j];
#pragma unroll
            for (int i = 0; i < 8; i++) {
                float av = ((const float*)&a[i])[kk];
#pragma unroll
                for (int j = 0; j < 5; j++) acc[i][j] += av * b[j];
            }
        }
    }
    float br[5];
#pragma unroll
    for (int j = 0; j < 5; j++) br[j] = bias[tc * 5 + j];
#pragma unroll
    for (int i = 0; i < 8; i++) {
        int row = r0 + tr * 8 + i;
        if (row < n) {
#pragma unroll
            for (int j = 0; j < 5; j++)
                out[(size_t)row * 40 + tc * 5 + j] = acc[i][j] + br[j];
        }
    }
}

// ---------------- launcher -------------------------------------------------
extern "C" void kernel_launch(void* const* d_in, const int* in_sizes, int n_in,
                              void* d_out, int out_size)
{
    const float* x  = (const float*)d_in[0];
    const void*  ei = d_in[1];
    const float* W0 = (const float*)d_in[2];
    const float* b0 = (const float*)d_in[3];
    const float* W1 = (const float*)d_in[4];
    const float* b1 = (const float*)d_in[5];
    const float* W2 = (const float*)d_in[6];
    const float* b2 = (const float*)d_in[7];
    const float* Wl = (const float*)d_in[8];
    const float* bl = (const float*)d_in[9];
    float* out = (float*)d_out;

    int n = in_sizes[0] / HDIM;
    int E = in_sizes[1] / 2;

    float *bufA, *bufB, *sums, *bnm, *bns;
    __nv_bfloat16 *whi, *wlo;
    cudaGetSymbolAddress((void**)&bufA, g_bufA);
    cudaGetSymbolAddress((void**)&bufB, g_bufB);
    cudaGetSymbolAddress((void**)&sums, g_sums);
    cudaGetSymbolAddress((void**)&bnm,  g_bnm);
    cudaGetSymbolAddress((void**)&bns,  g_bns);
    cudaGetSymbolAddress((void**)&whi,  g_Whi);
    cudaGetSymbolAddress((void**)&wlo,  g_Wlo);

    cudaFuncSetAttribute(k_gemm_mma, cudaFuncAttributeMaxDynamicSharedMemorySize, SMEM_MMA);
    cudaFuncSetAttribute(k_gemm40,   cudaFuncAttributeMaxDynamicSharedMemorySize, SMEM40);

    int nb = (n + 1023) >> 10;

    // CSR build (once; reused by all 3 layers)
    k_init<<<256, 256>>>(n);
    k_detect<<<16, 256>>>((const unsigned*)ei, in_sizes[1]);
    k_count<<<(E + 255) / 256, 256>>>(ei, E, n);
    k_scan1<<<nb, 256>>>(n);
    k_scan2<<<1, 128>>>(nb);
    k_scan3<<<(n + 255) / 256, 256>>>(n);
    k_scatter<<<(E + 255) / 256, 256>>>(ei, E, n);

    // weight prep (independent of CSR)
    k_wprep<<<64, 256>>>(W0, 0);
    k_wprep<<<64, 256>>>(W1, 1);
    k_wprep<<<64, 256>>>(W2, 2);

    const float* bs_[3] = { b0, b1, b2 };
    float* bufs[2] = { bufA, bufB };
    const float* P = x;
    int ngrid = (n + 63) / 64;
    for (int l = 0; l < 3; l++) {
        float* Q = bufs[l & 1];
        const float* pm  = (l == 0) ? nullptr : bnm + (l - 1) * 128;
        const float* psd = (l == 0) ? nullptr : bns + (l - 1) * 128;
        k_aggregate<<<(n * 32 + 255) / 256, 256>>>(P, Q, n, pm, psd);
        k_gemm_mma<<<ngrid, 128, SMEM_MMA>>>(Q, whi + l * 16384, wlo + l * 16384,
                                             bs_[l], sums + l * 256,
                                             sums + l * 256 + 128, n);
        k_bnfin<<<1, 128>>>(l, n);
        P = Q;
    }
    k_gemm40<<<(n + 127) / 128, 128, SMEM40>>>(P, Wl, bl, out, n,
                                               bnm + 2 * 128, bns + 2 * 128);
}

// round 7
// speedup vs baseline: 1.7581x; 1.2286x over previous
#include <cuda_runtime.h>
#include <cuda_bf16.h>
#include <cstdint>

#define NMAX 100000
#define EMAX 800000
#define HDIM 128

// ---------------- static device scratch ------------------------------------
__device__ float g_bufA[NMAX * HDIM];
__device__ float g_bufB[NMAX * HDIM];
__device__ int   g_count[NMAX];
__device__ int   g_excl[NMAX];
__device__ int   g_rowstart[NMAX + 1];
__device__ int   g_cursor[NMAX];
__device__ int   g_col[EMAX];
__device__ int   g_bsum[128];
__device__ float g_sums[6 * 128];            // [layer][sum(128)|sumsq(128)]
__device__ float g_bnm[3 * 128];             // per-layer mean
__device__ float g_bns[3 * 128];             // per-layer rsqrt(var+eps)
__device__ __nv_bfloat16 g_Whi[3 * 16384];   // row-major [k][n] bf16 hi
__device__ __nv_bfloat16 g_Wlo[3 * 16384];   // row-major [k][n] bf16 lo
__device__ int   g_is64;

// ---------------- helpers ---------------------------------------------------
__device__ __forceinline__ uint32_t smem_u32(const void* p) {
    uint32_t a;
    asm("{ .reg .u64 t; cvta.to.shared.u64 t, %1; cvt.u32.u64 %0, t; }" : "=r"(a) : "l"(p));
    return a;
}
__device__ __forceinline__ void ldsm4(uint32_t* r, uint32_t addr) {
    asm volatile("ldmatrix.sync.aligned.m8n8.x4.shared.b16 {%0,%1,%2,%3}, [%4];"
                 : "=r"(r[0]), "=r"(r[1]), "=r"(r[2]), "=r"(r[3]) : "r"(addr));
}
__device__ __forceinline__ void ldsm4t(uint32_t* r, uint32_t addr) {
    asm volatile("ldmatrix.sync.aligned.m8n8.x4.trans.shared.b16 {%0,%1,%2,%3}, [%4];"
                 : "=r"(r[0]), "=r"(r[1]), "=r"(r[2]), "=r"(r[3]) : "r"(addr));
}
__device__ __forceinline__ void mma16816(float* d, const uint32_t* a, const uint32_t* b) {
    asm volatile("mma.sync.aligned.m16n8k16.row.col.f32.bf16.bf16.f32 "
                 "{%0,%1,%2,%3}, {%4,%5,%6,%7}, {%8,%9}, {%0,%1,%2,%3};"
                 : "+f"(d[0]), "+f"(d[1]), "+f"(d[2]), "+f"(d[3])
                 : "r"(a[0]), "r"(a[1]), "r"(a[2]), "r"(a[3]), "r"(b[0]), "r"(b[1]));
}
__device__ __forceinline__ float4 bn_relu4(float4 v, float4 m4, float4 s4) {
    v.x = fmaxf((v.x - m4.x) * s4.x, 0.f);
    v.y = fmaxf((v.y - m4.y) * s4.y, 0.f);
    v.z = fmaxf((v.z - m4.z) * s4.z, 0.f);
    v.w = fmaxf((v.w - m4.w) * s4.w, 0.f);
    return v;
}

// ---------------- init + dtype detection -----------------------------------
__global__ void k_init(int n) {
    int i  = blockIdx.x * blockDim.x + threadIdx.x;
    int st = gridDim.x * blockDim.x;
    for (int k = i; k < n; k += st) g_count[k] = 0;
    for (int k = i; k < 6 * 128; k += st) g_sums[k] = 0.f;
    if (i == 0) g_is64 = 1;
}
__global__ void k_detect(const unsigned* __restrict__ w, int nwords) {
    int i = blockIdx.x * blockDim.x + threadIdx.x;
    int idx = 2 * i + 1;
    if (i < 4096 && idx < nwords) {
        if (w[idx] != 0u) atomicExch(&g_is64, 0);
    }
}
__device__ __forceinline__ int load_idx(const void* ei, long long pos, int is64) {
    if (is64) return (int)((const long long*)ei)[pos];
    return ((const int*)ei)[pos];
}

// ---------------- CSR build ------------------------------------------------
__global__ void k_count(const void* __restrict__ ei, int E, int n) {
    int is64 = g_is64;
    int i  = blockIdx.x * blockDim.x + threadIdx.x;
    int st = gridDim.x * blockDim.x;
    for (int e = i; e < E; e += st) {
        int d = load_idx(ei, e, is64);
        if ((unsigned)d < (unsigned)n) atomicAdd(&g_count[d], 1);
    }
}
__global__ void k_scan1(int n) {
    __shared__ int s[256];
    int tid  = threadIdx.x;
    int base = blockIdx.x * 1024 + tid * 4;
    int v[4];
#pragma unroll
    for (int i = 0; i < 4; i++) v[i] = (base + i < n) ? g_count[base + i] : 0;
    int tsum = v[0] + v[1] + v[2] + v[3];
    s[tid] = tsum;
    __syncthreads();
#pragma unroll
    for (int off = 1; off < 256; off <<= 1) {
        int x = (tid >= off) ? s[tid - off] : 0;
        __syncthreads();
        s[tid] += x;
        __syncthreads();
    }
    int run = s[tid] - tsum;
#pragma unroll
    for (int i = 0; i < 4; i++) {
        if (base + i < n) g_excl[base + i] = run;
        run += v[i];
    }
    if (tid == 255) g_bsum[blockIdx.x] = s[255];
}
__global__ void k_scan2(int nb) {
    __shared__ int s[128];
    int tid = threadIdx.x;
    int v   = (tid < nb) ? g_bsum[tid] : 0;
    s[tid] = v;
    __syncthreads();
#pragma unroll
    for (int off = 1; off < 128; off <<= 1) {
        int x = (tid >= off) ? s[tid - off] : 0;
        __syncthreads();
        s[tid] += x;
        __syncthreads();
    }
    if (tid < nb) g_bsum[tid] = s[tid] - v;
}
__global__ void k_scan3(int n) {
    int i  = blockIdx.x * blockDim.x + threadIdx.x;
    int st = gridDim.x * blockDim.x;
    for (int k = i; k < n; k += st) {
        int r = g_excl[k] + g_bsum[k >> 10];
        g_rowstart[k] = r;
        g_cursor[k]   = r;
    }
    if (i == 0)
        g_rowstart[n] = g_excl[n - 1] + g_bsum[(n - 1) >> 10] + g_count[n - 1];
}
__global__ void k_scatter(const void* __restrict__ ei, int E, int n) {
    int is64 = g_is64;
    int i  = blockIdx.x * blockDim.x + threadIdx.x;
    int st = gridDim.x * blockDim.x;
    for (int e = i; e < E; e += st) {
        int d = load_idx(ei, e, is64);
        if ((unsigned)d >= (unsigned)n) continue;
        int s = load_idx(ei, (long long)E + e, is64);
        if ((unsigned)s >= (unsigned)n) s = d;
        int p = atomicAdd(&g_cursor[d], 1);
        if ((unsigned)p < (unsigned)EMAX) g_col[p] = s;
    }
}

// ---------------- weight prep: fp32 [k][n] -> row-major bf16 hi/lo ----------
__global__ void k_wprep(const float* __restrict__ W, int l) {
    int idx = blockIdx.x * blockDim.x + threadIdx.x;
    if (idx >= 16384) return;
    float v = W[idx];
    __nv_bfloat16 hi = __float2bfloat16_rn(v);
    __nv_bfloat16 lo = __float2bfloat16_rn(v - __bfloat162float(hi));
    g_Whi[l * 16384 + idx] = hi;
    g_Wlo[l * 16384 + idx] = lo;
}

// ---------------- aggregation (+ fused BN+ReLU of prev layer), MLP=8 -------
__global__ void k_aggregate(const float* __restrict__ P, float* __restrict__ Q, int n,
                            const float* __restrict__ bnm, const float* __restrict__ bns) {
    int warp = (blockIdx.x * blockDim.x + threadIdx.x) >> 5;
    int lane = threadIdx.x & 31;
    if (warp >= n) return;
    bool dobn = (bnm != nullptr);
    float4 m4 = make_float4(0.f, 0.f, 0.f, 0.f);
    float4 s4 = make_float4(1.f, 1.f, 1.f, 1.f);
    if (dobn) {
        m4 = ((const float4*)bnm)[lane];
        s4 = ((const float4*)bns)[lane];
    }
    const float4* P4 = (const float4*)P;
    float4 acc = P4[(size_t)warp * 32 + lane];
    if (dobn) acc = bn_relu4(acc, m4, s4);
    int s = g_rowstart[warp];
    int t = g_rowstart[warp + 1];
    for (int p = s; p < t; p += 32) {
        int cnt = min(32, t - p);
        int j = (lane < cnt) ? g_col[p + lane] : 0;
        int q = 0;
        for (; q + 8 <= cnt; q += 8) {          // 8 independent loads in flight
            int jj[8];
#pragma unroll
            for (int u = 0; u < 8; u++) jj[u] = __shfl_sync(0xffffffffu, j, q + u);
            float4 r[8];
#pragma unroll
            for (int u = 0; u < 8; u++) r[u] = P4[(size_t)jj[u] * 32 + lane];
#pragma unroll
            for (int u = 0; u < 8; u++) {
                float4 v = dobn ? bn_relu4(r[u], m4, s4) : r[u];
                acc.x += v.x; acc.y += v.y; acc.z += v.z; acc.w += v.w;
            }
        }
        for (; q + 4 <= cnt; q += 4) {
            int j0 = __shfl_sync(0xffffffffu, j, q);
            int j1 = __shfl_sync(0xffffffffu, j, q + 1);
            int j2 = __shfl_sync(0xffffffffu, j, q + 2);
            int j3 = __shfl_sync(0xffffffffu, j, q + 3);
            float4 r0 = P4[(size_t)j0 * 32 + lane];
            float4 r1 = P4[(size_t)j1 * 32 + lane];
            float4 r2 = P4[(size_t)j2 * 32 + lane];
            float4 r3 = P4[(size_t)j3 * 32 + lane];
            if (dobn) {
                r0 = bn_relu4(r0, m4, s4); r1 = bn_relu4(r1, m4, s4);
                r2 = bn_relu4(r2, m4, s4); r3 = bn_relu4(r3, m4, s4);
            }
            acc.x += r0.x + r1.x + r2.x + r3.x;
            acc.y += r0.y + r1.y + r2.y + r3.y;
            acc.z += r0.z + r1.z + r2.z + r3.z;
            acc.w += r0.w + r1.w + r2.w + r3.w;
        }
        for (; q < cnt; q++) {
            int jj = __shfl_sync(0xffffffffu, j, q);
            float4 r = P4[(size_t)jj * 32 + lane];
            if (dobn) r = bn_relu4(r, m4, s4);
            acc.x += r.x; acc.y += r.y; acc.z += r.z; acc.w += r.w;
        }
    }
    ((float4*)Q)[(size_t)warp * 32 + lane] = acc;
}

// ---------------- persistent mma.sync bf16 GEMM + bias + BN stats -----------
// 3-term bf16 split: D = Ahi*Whi + Alo*Whi + Ahi*Wlo.  128 thr, 4 warps,
// warp = 16 rows x 128 cols.  64 rows/tile; W tiles loaded ONCE per CTA.
#define PA 136
#define ATILEB (64 * PA * 2)            // 17408 B
#define WTILEB (128 * PA * 2)           // 34816 B
#define OFF_AHI 0
#define OFF_ALO ATILEB
#define OFF_WHI (2 * ATILEB)
#define OFF_WLO (2 * ATILEB + WTILEB)
#define SMEM_MMA (2 * ATILEB + 2 * WTILEB)   // 104448 B -> 2 CTAs/SM

__global__ __launch_bounds__(128) void k_gemm_mma(
    float* __restrict__ A, const __nv_bfloat16* __restrict__ Whi,
    const __nv_bfloat16* __restrict__ Wlo, const float* __restrict__ bias,
    float* __restrict__ gsum, float* __restrict__ gsq, int n, int ntiles)
{
    extern __shared__ char sm[];
    int tid  = threadIdx.x;
    int lane = tid & 31;
    int warp = tid >> 5;

    // ---- W hi/lo tiles: load once ------------------------------------------
    for (int i = tid; i < 4096; i += 128) {     // k = i>>5, c4 = (i&31)*4
        int k = i >> 5, c4 = (i & 31) * 4;
        uint2 h = *(const uint2*)((const char*)Whi + k * 256 + c4 * 2);
        uint2 l = *(const uint2*)((const char*)Wlo + k * 256 + c4 * 2);
        *(uint2*)(sm + OFF_WHI + k * (PA * 2) + c4 * 2) = h;
        *(uint2*)(sm + OFF_WLO + k * (PA * 2) + c4 * 2) = l;
    }

    // per-lane fragment addressing (constant across tiles)
    int m  = lane >> 3, ri = lane & 7;
    int rowAl = warp * 16 + (m & 1) * 8 + ri;
    uint32_t aHiB = smem_u32(sm + OFF_AHI) + rowAl * (PA * 2) + (m >> 1) * 16;
    uint32_t aLoB = smem_u32(sm + OFF_ALO) + rowAl * (PA * 2) + (m >> 1) * 16;
    int rowB = lane & 15;                       // k-row within chunk
    uint32_t bHiB = smem_u32(sm + OFF_WHI) + rowB * (PA * 2) + (lane >> 4) * 16;
    uint32_t bLoB = smem_u32(sm + OFF_WLO) + rowB * (PA * 2) + (lane >> 4) * 16;

    const float4* A4 = (const float4*)A;
    float* sred  = (float*)sm;            // [4][128], aliases A tile region
    float* sredq = (float*)sm + 512;

    for (int tile = blockIdx.x; tile < ntiles; tile += gridDim.x) {
        int r0g = tile * 64;
        __syncthreads();   // previous iteration's stats reads done

        // ---- fill A hi/lo tiles (64 rows) ----------------------------------
        for (int i = tid; i < 2048; i += 128) {
            int row = i >> 5, c4 = (i & 31) * 4;
            float4 v = make_float4(0.f, 0.f, 0.f, 0.f);
            if (r0g + row < n) v = A4[(size_t)(r0g + row) * 32 + (i & 31)];
            __nv_bfloat16 h0 = __float2bfloat16_rn(v.x), h1 = __float2bfloat16_rn(v.y);
            __nv_bfloat16 h2 = __float2bfloat16_rn(v.z), h3 = __float2bfloat16_rn(v.w);
            __nv_bfloat16 l0 = __float2bfloat16_rn(v.x - __bfloat162float(h0));
            __nv_bfloat16 l1 = __float2bfloat16_rn(v.y - __bfloat162float(h1));
            __nv_bfloat16 l2 = __float2bfloat16_rn(v.z - __bfloat162float(h2));
            __nv_bfloat16 l3 = __float2bfloat16_rn(v.w - __bfloat162float(h3));
            uint2 ph = make_uint2(
                (uint32_t)__bfloat16_as_ushort(h0) | ((uint32_t)__bfloat16_as_ushort(h1) << 16),
                (uint32_t)__bfloat16_as_ushort(h2) | ((uint32_t)__bfloat16_as_ushort(h3) << 16));
            uint2 pl = make_uint2(
                (uint32_t)__bfloat16_as_ushort(l0) | ((uint32_t)__bfloat16_as_ushort(l1) << 16),
                (uint32_t)__bfloat16_as_ushort(l2) | ((uint32_t)__bfloat16_as_ushort(l3) << 16));
            *(uint2*)(sm + OFF_AHI + row * (PA * 2) + c4 * 2) = ph;
            *(uint2*)(sm + OFF_ALO + row * (PA * 2) + c4 * 2) = pl;
        }
        __syncthreads();

        // ---- mma mainloop (B via x4.trans: 2 n-tiles per LDSM) -------------
        float acc[16][4];
#pragma unroll
        for (int t = 0; t < 16; t++)
#pragma unroll
            for (int j = 0; j < 4; j++) acc[t][j] = 0.f;

#pragma unroll
        for (int kc = 0; kc < 8; kc++) {
            uint32_t ah[4], al[4];
            ldsm4(ah, aHiB + kc * 32);
            ldsm4(al, aLoB + kc * 32);
            uint32_t kb = kc * 16 * (PA * 2);
#pragma unroll
            for (int nt = 0; nt < 8; nt++) {
                uint32_t bh[4], bl[4];
                ldsm4t(bh, bHiB + kb + nt * 32);
                ldsm4t(bl, bLoB + kb + nt * 32);
                mma16816(acc[2 * nt],     ah, bh);
                mma16816(acc[2 * nt],     al, bh);
                mma16816(acc[2 * nt],     ah, bl);
                mma16816(acc[2 * nt + 1], ah, bh + 2);
                mma16816(acc[2 * nt + 1], al, bh + 2);
                mma16816(acc[2 * nt + 1], ah, bl + 2);
            }
        }
        __syncthreads();   // A tiles dead; sred aliases them

        // ---- epilogue: bias, store, BN partial stats -----------------------
        int lr = lane >> 2;
        int lc = lane & 3;
        int row0 = r0g + warp * 16 + lr;
        int row1 = row0 + 8;
        bool v0 = row0 < n, v1 = row1 < n;
#pragma unroll
        for (int nt = 0; nt < 16; nt++) {
            int c0 = nt * 8 + lc * 2;
            float b0v = __ldg(bias + c0), b1v = __ldg(bias + c0 + 1);
            float y00 = acc[nt][0] + b0v, y01 = acc[nt][1] + b1v;
            float y10 = acc[nt][2] + b0v, y11 = acc[nt][3] + b1v;
            if (v0) *(float2*)&A[(size_t)row0 * 128 + c0] = make_float2(y00, y01);
            if (v1) *(float2*)&A[(size_t)row1 * 128 + c0] = make_float2(y10, y11);
            float s0 = (v0 ? y00 : 0.f) + (v1 ? y10 : 0.f);
            float s1 = (v0 ? y01 : 0.f) + (v1 ? y11 : 0.f);
            float q0 = (v0 ? y00 * y00 : 0.f) + (v1 ? y10 * y10 : 0.f);
            float q1 = (v0 ? y01 * y01 : 0.f) + (v1 ? y11 * y11 : 0.f);
#pragma unroll
            for (int o = 4; o < 32; o <<= 1) {
                s0 += __shfl_xor_sync(0xffffffffu, s0, o);
                s1 += __shfl_xor_sync(0xffffffffu, s1, o);
                q0 += __shfl_xor_sync(0xffffffffu, q0, o);
                q1 += __shfl_xor_sync(0xffffffffu, q1, o);
            }
            if (lr == 0) {
                sred [warp * 128 + c0]     = s0;
                sred [warp * 128 + c0 + 1] = s1;
                sredq[warp * 128 + c0]     = q0;
                sredq[warp * 128 + c0 + 1] = q1;
            }
        }
        __syncthreads();
        if (tid < 128) {
            float s = 0.f, q = 0.f;
#pragma unroll
            for (int w = 0; w < 4; w++) {
                s += sred [w * 128 + tid];
                q += sredq[w * 128 + tid];
            }
            atomicAdd(&gsum[tid], s);
            atomicAdd(&gsq[tid], q);
        }
    }
}

// ---------------- BN finalize (per layer, tiny) -----------------------------
__global__ void k_bnfin(int l, int n) {
    int c = threadIdx.x;
    float inv_n = 1.0f / (float)n;
    float m = g_sums[l * 256 + c] * inv_n;
    float v = g_sums[l * 256 + 128 + c] * inv_n - m * m;
    g_bnm[l * 128 + c] = m;
    g_bns[l * 128 + c] = rsqrtf(v + 1e-5f);
}

// ---------------- final GEMM 128 -> 40 + bias (BN+ReLU fused on load) ------
#define SMEM40 ((128 * 132 + 128 * 40) * 4)
__global__ __launch_bounds__(128) void k_gemm40(
    const float* __restrict__ A, const float* __restrict__ W,
    const float* __restrict__ bias, float* __restrict__ out, int n,
    const float* __restrict__ bnm, const float* __restrict__ bns)
{
    extern __shared__ float smf[];
    float* As = smf;              // [128][132]
    float* Ws = smf + 128 * 132;  // [128][40]
    int tid = threadIdx.x;
    int r0  = blockIdx.x * 128;

    for (int i = tid; i < 4096; i += 128) {
        int row = i >> 5, k4 = i & 31;
        float4 v = make_float4(0.f, 0.f, 0.f, 0.f);
        if (r0 + row < n) {
            v = ((const float4*)A)[(size_t)(r0 + row) * 32 + k4];
            float4 m4 = ((const float4*)bnm)[k4];
            float4 s4 = ((const float4*)bns)[k4];
            v = bn_relu4(v, m4, s4);
        }
        float* d = &As[row * 132 + k4 * 4];
        d[0] = v.x; d[1] = v.y; d[2] = v.z; d[3] = v.w;
    }
    for (int i = tid; i < 1280; i += 128)
        ((float4*)Ws)[i] = ((const float4*)W)[i];
    __syncthreads();

    int tr = tid >> 3;   // 0..15 -> rows tr*8 .. +7
    int tc = tid & 7;    // 0..7  -> cols tc*5 .. +4
    float acc[8][5];
#pragma unroll
    for (int i = 0; i < 8; i++)
#pragma unroll
        for (int j = 0; j < 5; j++) acc[i][j] = 0.f;

    for (int k = 0; k < 128; k += 4) {
        float4 a[8];
#pragma unroll
        for (int i = 0; i < 8; i++) a[i] = *(const float4*)&As[(tr * 8 + i) * 132 + k];
#pragma unroll
        for (int kk = 0; kk < 4; kk++) {
            float b[5];
#pragma unroll
            for (int j = 0; j < 5; j++) b[j] = Ws[(k + kk) * 40 + tc * 5 + j];
#pragma unroll
            for (int i = 0; i < 8; i++) {
                float av = ((const float*)&a[i])[kk];
#pragma unroll
                for (int j = 0; j < 5; j++) acc[i][j] += av * b[j];
            }
        }
    }
    float br[5];
#pragma unroll
    for (int j = 0; j < 5; j++) br[j] = bias[tc * 5 + j];
#pragma unroll
    for (int i = 0; i < 8; i++) {
        int row = r0 + tr * 8 + i;
        if (row < n) {
#pragma unroll
            for (int j = 0; j < 5; j++)
                out[(size_t)row * 40 + tc * 5 + j] = acc[i][j] + br[j];
        }
    }
}

// ---------------- launcher -------------------------------------------------
extern "C" void kernel_launch(void* const* d_in, const int* in_sizes, int n_in,
                              void* d_out, int out_size)
{
    const float* x  = (const float*)d_in[0];
    const void*  ei = d_in[1];
    const float* W0 = (const float*)d_in[2];
    const float* b0 = (const float*)d_in[3];
    const float* W1 = (const float*)d_in[4];
    const float* b1 = (const float*)d_in[5];
    const float* W2 = (const float*)d_in[6];
    const float* b2 = (const float*)d_in[7];
    const float* Wl = (const float*)d_in[8];
    const float* bl = (const float*)d_in[9];
    float* out = (float*)d_out;

    int n = in_sizes[0] / HDIM;
    int E = in_sizes[1] / 2;

    float *bufA, *bufB, *sums, *bnm, *bns;
    __nv_bfloat16 *whi, *wlo;
    cudaGetSymbolAddress((void**)&bufA, g_bufA);
    cudaGetSymbolAddress((void**)&bufB, g_bufB);
    cudaGetSymbolAddress((void**)&sums, g_sums);
    cudaGetSymbolAddress((void**)&bnm,  g_bnm);
    cudaGetSymbolAddress((void**)&bns,  g_bns);
    cudaGetSymbolAddress((void**)&whi,  g_Whi);
    cudaGetSymbolAddress((void**)&wlo,  g_Wlo);

    cudaFuncSetAttribute(k_gemm_mma, cudaFuncAttributeMaxDynamicSharedMemorySize, SMEM_MMA);
    cudaFuncSetAttribute(k_gemm40,   cudaFuncAttributeMaxDynamicSharedMemorySize, SMEM40);

    int nb = (n + 1023) >> 10;

    // CSR build (once; reused by all 3 layers)
    k_init<<<256, 256>>>(n);
    k_detect<<<16, 256>>>((const unsigned*)ei, in_sizes[1]);
    k_count<<<(E + 255) / 256, 256>>>(ei, E, n);
    k_scan1<<<nb, 256>>>(n);
    k_scan2<<<1, 128>>>(nb);
    k_scan3<<<(n + 255) / 256, 256>>>(n);
    k_scatter<<<(E + 255) / 256, 256>>>(ei, E, n);

    // weight prep (independent of CSR)
    k_wprep<<<64, 256>>>(W0, 0);
    k_wprep<<<64, 256>>>(W1, 1);
    k_wprep<<<64, 256>>>(W2, 2);

    const float* bs_[3] = { b0, b1, b2 };
    float* bufs[2] = { bufA, bufB };
    const float* P = x;
    int ntiles = (n + 63) / 64;
    int ggrid  = ntiles < 296 ? ntiles : 296;   // 2 CTAs/SM persistent
    for (int l = 0; l < 3; l++) {
        float* Q = bufs[l & 1];
        const float* pm  = (l == 0) ? nullptr : bnm + (l - 1) * 128;
        const float* psd = (l == 0) ? nullptr : bns + (l - 1) * 128;
        k_aggregate<<<(n * 32 + 255) / 256, 256>>>(P, Q, n, pm, psd);
        k_gemm_mma<<<ggrid, 128, SMEM_MMA>>>(Q, whi + l * 16384, wlo + l * 16384,
                                             bs_[l], sums + l * 256,
                                             sums + l * 256 + 128, n, ntiles);
        k_bnfin<<<1, 128>>>(l, n);
        P = Q;
    }
    k_gemm40<<<(n + 127) / 128, 128, SMEM40>>>(P, Wl, bl, out, n,
                                               bnm + 2 * 128, bns + 2 * 128);
}